// round 10
// baseline (speedup 1.0000x reference)
#include <cuda_runtime.h>
#include <cuda_fp16.h>

#define D      128
#define H0     64
#define W0     96
#define NPIX0  (H0*W0)        // 6144
#define NPIX_T 8160           // 6144+1536+384+96

__device__ __align__(16) __half g_f1h[NPIX_T * D];   // fp16 channel-last, all levels
__device__ __align__(16) __half g_f2h[NPIX_T * D];   // fp16 channel-last, all levels
__device__ float  g_crd [NPIX_T * 2];
__device__ float  g_tmpA[5376 * 2];                  // x-resized coords, levels 1-3

__constant__ int c_HL[4] = {64, 32, 16, 8};
__constant__ int c_WL[4] = {96, 48, 24, 12};
__constant__ int c_PO[4] = {0, 6144, 7680, 8064};
__constant__ int c_OO[4] = {0, 81*6144, 81*7680, 81*8064};

// ---------------------------------------------------------------------------
// Transpose (D,HW)->(HW,D) fp32 -> fp16, both maps. 768 blocks, two 32x32
// tiles per block -> 2 independent LDG.128 per thread.
// ---------------------------------------------------------------------------
__global__ void __launch_bounds__(256) k_tr(const float* __restrict__ f1,
                                            const float* __restrict__ f2) {
    __shared__ float tile[2][32 * 33];
    int b  = blockIdx.x;
    int bx = b % 192;            // pixel tile (32 px)
    int by = (b / 192) & 1;      // 64-channel tile
    int z  = b / 384;            // map
    const float* src = z ? f2 : f1;
    int p0 = bx * 32, d0 = by * 64;
    int drow = threadIdx.x >> 3;
    int px4  = threadIdx.x & 7;
    const float* s0 = src + (size_t)(d0 + drow) * NPIX0 + p0 + px4 * 4;
    float4 v0 = *(const float4*)(s0);
    float4 v1 = *(const float4*)(s0 + 32 * NPIX0);
    float* t0 = &tile[0][drow * 33 + px4 * 4];
    float* t1 = &tile[1][drow * 33 + px4 * 4];
    t0[0] = v0.x; t0[1] = v0.y; t0[2] = v0.z; t0[3] = v0.w;
    t1[0] = v1.x; t1[1] = v1.y; t1[2] = v1.z; t1[3] = v1.w;
    __syncthreads();
    __half* dst = z ? g_f2h : g_f1h;
    int sd = threadIdx.x & 15;
    int sp = threadIdx.x >> 4;
    #pragma unroll
    for (int k = 0; k < 2; k++) {
        #pragma unroll
        for (int i = 0; i < 2; i++) {
            int pl = sp + 16 * i;
            float lo = tile[k][(sd * 2)     * 33 + pl];
            float hi = tile[k][(sd * 2 + 1) * 33 + pl];
            *(__half2*)(dst + (size_t)(p0 + pl) * D + d0 + k * 32 + sd * 2) =
                __floats2half2_rn(lo, hi);
        }
    }
}

// ---------------------------------------------------------------------------
// coordsA: level-0 coord copy + x-axis triangle resize (levels 1-3). 90 blocks.
// ---------------------------------------------------------------------------
#define CA_ELEMS (2*NPIX0 + 5376*2)
__global__ void __launch_bounds__(256) k_coordsA(const float* __restrict__ crd) {
    int idx = blockIdx.x * 256 + threadIdx.x;
    if (idx < 2 * NPIX0) {
        int q = idx >> 1, ax = idx & 1;
        g_crd[idx] = crd[ax * NPIX0 + q];
        return;
    }
    idx -= 2 * NPIX0;
    if (idx >= 5376 * 2) return;
    int p = idx >> 1, ax = idx & 1;
    int l, base;
    if      (p < 3072) { l = 1; base = 0;    }
    else if (p < 4608) { l = 2; base = 3072; }
    else               { l = 3; base = 4608; }
    int q  = p - base;
    int Wl = c_WL[l];
    int h  = q / Wl, w = q % Wl;
    float s   = (float)(1 << l);
    float cxx = (w + 0.5f) * s - 0.5f;
    int j0 = max(0,    (int)ceilf (cxx - s));
    int j1 = min(W0-1, (int)floorf(cxx + s));
    float sum = 0.f, acc = 0.f;
    for (int i = j0; i <= j1; i++) {
        float wgt = 1.f - fabsf(i - cxx) / s;
        sum += wgt;
        acc += wgt * crd[ax * NPIX0 + h * W0 + i];
    }
    g_tmpA[p * 2 + ax] = acc / sum;
}

// ---------------------------------------------------------------------------
// Hierarchical pool (levels 1..3, both maps) + coordsB, one kernel.
// Pool: block <-> (map, L3 pixel) = one 8x8 level-0 region. 256 threads,
// 4 independent float4 loads each (uniform), L1 in regs -> SMEM fp32 ->
// L2 -> L3. 192 pool blocks + 16 coordsB blocks.
// ---------------------------------------------------------------------------
__global__ void __launch_bounds__(256) k_pool_cb() {
    int b = blockIdx.x;
    if (b < 192) {
        __shared__ float sm1[16 * 128];   // 16 L1 px x 128 ch (fp32)
        __shared__ float sm2[4 * 128];    // 4  L2 px x 128 ch
        int m  = b >= 96;
        int p3 = m ? b - 96 : b;
        int h3 = p3 / 12, w3 = p3 % 12;
        __half* arr = m ? g_f2h : g_f1h;
        int t = threadIdx.x, grp = t & 15, l1 = t >> 4;
        int i1 = l1 >> 2, j1 = l1 & 3;
        int r0 = h3 * 8 + i1 * 2, c0 = w3 * 8 + j1 * 2;
        float2 a0 = {0,0}, a1 = {0,0}, a2 = {0,0}, a3 = {0,0};
        #pragma unroll
        for (int di = 0; di < 2; di++)
            #pragma unroll
            for (int dj = 0; dj < 2; dj++) {
                float4 hv = *(const float4*)(arr +
                    (size_t)((r0 + di) * W0 + (c0 + dj)) * D + grp * 8);
                const __half2* hh = (const __half2*)&hv;
                float2 v;
                v = __half22float2(hh[0]); a0.x += v.x; a0.y += v.y;
                v = __half22float2(hh[1]); a1.x += v.x; a1.y += v.y;
                v = __half22float2(hh[2]); a2.x += v.x; a2.y += v.y;
                v = __half22float2(hh[3]); a3.x += v.x; a3.y += v.y;
            }
        a0.x *= 0.25f; a0.y *= 0.25f; a1.x *= 0.25f; a1.y *= 0.25f;
        a2.x *= 0.25f; a2.y *= 0.25f; a3.x *= 0.25f; a3.y *= 0.25f;
        // store L1 (fp16)
        {
            __half2 r[4];
            r[0] = __floats2half2_rn(a0.x, a0.y);
            r[1] = __floats2half2_rn(a1.x, a1.y);
            r[2] = __floats2half2_rn(a2.x, a2.y);
            r[3] = __floats2half2_rn(a3.x, a3.y);
            int p1 = c_PO[1] + (h3 * 4 + i1) * 48 + (w3 * 4 + j1);
            *(float4*)(arr + (size_t)p1 * D + grp * 8) = *(float4*)r;
        }
        float* s1 = sm1 + l1 * 128 + grp * 8;
        s1[0] = a0.x; s1[1] = a0.y; s1[2] = a1.x; s1[3] = a1.y;
        s1[4] = a2.x; s1[5] = a2.y; s1[6] = a3.x; s1[7] = a3.y;
        __syncthreads();
        if (t < 64) {
            int g2 = t & 15, l2 = t >> 4;
            int i2 = l2 >> 1, j2 = l2 & 1;
            float acc[8];
            #pragma unroll
            for (int c = 0; c < 8; c++) acc[c] = 0.f;
            #pragma unroll
            for (int di = 0; di < 2; di++)
                #pragma unroll
                for (int dj = 0; dj < 2; dj++) {
                    const float* s = sm1 + ((2*i2 + di) * 4 + (2*j2 + dj)) * 128 + g2 * 8;
                    #pragma unroll
                    for (int c = 0; c < 8; c++) acc[c] += s[c];
                }
            __half2 r[4];
            #pragma unroll
            for (int c = 0; c < 4; c++)
                r[c] = __floats2half2_rn(acc[2*c] * 0.25f, acc[2*c+1] * 0.25f);
            int p2 = c_PO[2] + (h3 * 2 + i2) * 24 + (w3 * 2 + j2);
            *(float4*)(arr + (size_t)p2 * D + g2 * 8) = *(float4*)r;
            float* s2 = sm2 + l2 * 128 + g2 * 8;
            #pragma unroll
            for (int c = 0; c < 8; c++) s2[c] = acc[c] * 0.25f;
        }
        __syncthreads();
        if (t < 16) {
            float acc[8];
            #pragma unroll
            for (int c = 0; c < 8; c++) acc[c] = 0.f;
            #pragma unroll
            for (int l2 = 0; l2 < 4; l2++) {
                const float* s = sm2 + l2 * 128 + t * 8;
                #pragma unroll
                for (int c = 0; c < 8; c++) acc[c] += s[c];
            }
            __half2 r[4];
            #pragma unroll
            for (int c = 0; c < 4; c++)
                r[c] = __floats2half2_rn(acc[2*c] * 0.25f, acc[2*c+1] * 0.25f);
            int p3g = c_PO[3] + h3 * 12 + w3;
            *(float4*)(arr + (size_t)p3g * D + t * 8) = *(float4*)r;
        }
        return;
    }
    // ---- coordsB: y-axis resize + /2^l ----
    int idx = (b - 192) * 256 + threadIdx.x;
    if (idx >= 2016 * 2) return;
    int p = idx >> 1, ax = idx & 1;
    int l, base, abase;
    if      (p < 1536) { l = 1; base = 0;    abase = 0;    }
    else if (p < 1920) { l = 2; base = 1536; abase = 3072; }
    else               { l = 3; base = 1920; abase = 4608; }
    int q  = p - base;
    int Wl = c_WL[l];
    int h  = q / Wl, w = q % Wl;
    float s   = (float)(1 << l);
    float cyy = (h + 0.5f) * s - 0.5f;
    int j0 = max(0,    (int)ceilf (cyy - s));
    int j1 = min(H0-1, (int)floorf(cyy + s));
    float sum = 0.f, acc = 0.f;
    for (int j = j0; j <= j1; j++) {
        float wgt = 1.f - fabsf(j - cyy) / s;
        sum += wgt;
        acc += wgt * g_tmpA[(abase + j * Wl + w) * 2 + ax];
    }
    g_crd[(c_PO[l] + q) * 2 + ax] = acc / (sum * s);
}

// ---------------------------------------------------------------------------
// corr body (R5 scheme): warp<->pixel, 8-lane dot groups, ALU offsets.
// ---------------------------------------------------------------------------
#define TILE 8
__device__ __forceinline__ float dot8h(float4 a0, float4 a1, float4 hv) {
    const __half2* h = (const __half2*)&hv;
    float2 v0 = __half22float2(h[0]);
    float2 v1 = __half22float2(h[1]);
    float2 v2 = __half22float2(h[2]);
    float2 v3 = __half22float2(h[3]);
    return a0.x*v0.x + a0.y*v0.y + a0.z*v1.x + a0.w*v1.y
         + a1.x*v2.x + a1.y*v2.y + a1.z*v3.x + a1.w*v3.y;
}

__device__ __forceinline__ void corr_part(int l, int pix0, float* __restrict__ out) {
    int Hl = c_HL[l], Wl = c_WL[l];
    int pixoff = c_PO[l];
    int HW = Hl * Wl;

    int tid   = threadIdx.x;
    int lane  = tid & 31, warp = tid >> 5;
    int lane8 = lane & 7, grp = lane >> 3;

    __shared__ float gsh[TILE * 100];
    __shared__ float fxs[TILE], fys[TILE];
    __shared__ int   bxs[TILE], bys[TILE];

    int pix = pix0 + warp;

    const __half* f1row = g_f1h + (size_t)(pixoff + pix) * D;
    float4 ha = *(const float4*)(f1row + lane8 * 8);
    float4 hb = *(const float4*)(f1row + 64 + lane8 * 8);
    float4 a0, a1, a2, a3;
    {
        const __half2* pa = (const __half2*)&ha;
        float2 q0 = __half22float2(pa[0]), q1 = __half22float2(pa[1]);
        float2 q2 = __half22float2(pa[2]), q3 = __half22float2(pa[3]);
        a0 = make_float4(q0.x, q0.y, q1.x, q1.y);
        a1 = make_float4(q2.x, q2.y, q3.x, q3.y);
        const __half2* pb = (const __half2*)&hb;
        q0 = __half22float2(pb[0]); q1 = __half22float2(pb[1]);
        q2 = __half22float2(pb[2]); q3 = __half22float2(pb[3]);
        a2 = make_float4(q0.x, q0.y, q1.x, q1.y);
        a3 = make_float4(q2.x, q2.y, q3.x, q3.y);
    }

    float cx = 0.f, cy = 0.f;
    if (lane == 0) {
        cx = g_crd[(pixoff + pix) * 2];
        cy = g_crd[(pixoff + pix) * 2 + 1];
    }
    cx = __shfl_sync(0xffffffffu, cx, 0);
    cy = __shfl_sync(0xffffffffu, cy, 0);
    float flx = floorf(cx), fly = floorf(cy);
    int bx = (int)flx, by = (int)fly;
    if (lane == 0) {
        bxs[warp] = bx; bys[warp] = by;
        fxs[warp] = cx - flx; fys[warp] = cy - fly;
    }

    const __half* f2lane = g_f2h + (size_t)pixoff * D + lane8 * 8;
    float* gsh100 = gsh + warp * 100;

    #pragma unroll 5
    for (int i = 0; i < 25; i++) {
        int pos = i * 4 + grp;
        int u = (pos * 205) >> 11;       // pos / 10
        int t = pos - u * 10;            // pos % 10
        int px = min(max(bx + t - 4, 0), Wl - 1);
        int py = min(max(by + u - 4, 0), Hl - 1);
        const __half* row = f2lane + (py * Wl + px) * D;
        float4 h0 = *(const float4*)(row);
        float4 h1 = *(const float4*)(row + 64);
        float s = dot8h(a0, a1, h0) + dot8h(a2, a3, h1);
        s += __shfl_xor_sync(0xffffffffu, s, 4);
        s += __shfl_xor_sync(0xffffffffu, s, 2);
        s += __shfl_xor_sync(0xffffffffu, s, 1);
        if (lane8 == 0) gsh100[pos] = s;
    }
    __syncthreads();

    #pragma unroll
    for (int idx = tid; idx < 81 * TILE; idx += 256) {
        int k = idx >> 3;
        int j = idx & (TILE - 1);
        int adx = k / 9;
        int bdy = k - adx * 9;
        int t0 = bxs[j] + adx - 4;
        int u0 = bys[j] + bdy - 4;
        float wx1 = (t0 < 0 || t0 >= Wl - 1) ? 0.f : fxs[j];
        float wy1 = (u0 < 0 || u0 >= Hl - 1) ? 0.f : fys[j];
        float wx0 = 1.f - wx1, wy0 = 1.f - wy1;
        const float* g = gsh + j * 100 + bdy * 10 + adx;
        float c = wy0 * (wx0 * g[0]  + wx1 * g[1])
                + wy1 * (wx0 * g[10] + wx1 * g[11]);
        out[c_OO[l] + k * HW + pix0 + j] = c * 0.08838834764831845f; // 1/sqrt(128)
    }
}

__global__ void __launch_bounds__(256) k_corr0(float* __restrict__ out) {
    corr_part(0, blockIdx.x * TILE, out);
}

__global__ void __launch_bounds__(256) k_corr123(float* __restrict__ out) {
    int bb = blockIdx.x;
    int l, tbase;
    if      (bb < 192) { l = 1; tbase = 0;   }
    else if (bb < 240) { l = 2; tbase = 192; }
    else               { l = 3; tbase = 240; }
    corr_part(l, (bb - tbase) * TILE, out);
}

// ---------------------------------------------------------------------------
// Launch graph:
//   s0: TR --------------------------> [wait CA] corr0 [wait S2] join
//   s1: coordsA
//   s2: [wait TR][wait CA] pool+coordsB -> corr123
// ---------------------------------------------------------------------------
extern "C" void kernel_launch(void* const* d_in, const int* in_sizes, int n_in,
                              void* d_out, int out_size) {
    const float* f1  = (const float*)d_in[0];
    const float* f2  = (const float*)d_in[1];
    const float* crd = (const float*)d_in[2];
    float* out = (float*)d_out;

    static cudaStream_t s1 = nullptr, s2 = nullptr;
    static cudaEvent_t evRoot = nullptr, evTR = nullptr, evCA = nullptr,
                       evS2 = nullptr;
    if (!s1) {
        cudaStreamCreateWithFlags(&s1, cudaStreamNonBlocking);
        cudaStreamCreateWithFlags(&s2, cudaStreamNonBlocking);
        cudaEventCreateWithFlags(&evRoot, cudaEventDisableTiming);
        cudaEventCreateWithFlags(&evTR,   cudaEventDisableTiming);
        cudaEventCreateWithFlags(&evCA,   cudaEventDisableTiming);
        cudaEventCreateWithFlags(&evS2,   cudaEventDisableTiming);
    }

    // fork
    cudaEventRecord(evRoot, 0);
    cudaStreamWaitEvent(s1, evRoot, 0);
    cudaStreamWaitEvent(s2, evRoot, 0);

    // branch B (s1): coordsA
    k_coordsA<<<(CA_ELEMS + 255) / 256, 256, 0, s1>>>(crd);
    cudaEventRecord(evCA, s1);

    // branch A (s0): transpose
    k_tr<<<768, 256>>>(f1, f2);
    cudaEventRecord(evTR, 0);

    // branch C (s2): pool+coordsB -> corr levels 1-3
    cudaStreamWaitEvent(s2, evTR, 0);
    cudaStreamWaitEvent(s2, evCA, 0);
    k_pool_cb<<<208, 256, 0, s2>>>();
    k_corr123<<<252, 256, 0, s2>>>(out);
    cudaEventRecord(evS2, s2);

    // branch A continues: corr level 0
    cudaStreamWaitEvent(0, evCA, 0);
    k_corr0<<<768, 256>>>(out);

    // join
    cudaStreamWaitEvent(0, evS2, 0);
}

// round 13
// speedup vs baseline: 1.0550x; 1.0550x over previous
#include <cuda_runtime.h>
#include <cuda_fp16.h>

#define D      128
#define H0     64
#define W0     96
#define NPIX0  (H0*W0)        // 6144
#define NPIX_T 8160           // 6144+1536+384+96

__device__ __align__(16) __half g_f1h[NPIX_T * D];   // fp16 channel-last, all levels
__device__ __align__(16) __half g_f2h[NPIX_T * D];   // fp16 channel-last, all levels
__device__ float  g_crd [NPIX_T * 2];
__device__ float  g_tmpA[5376 * 2];                  // x-resized coords, levels 1-3

__constant__ int c_HL[4] = {64, 32, 16, 8};
__constant__ int c_WL[4] = {96, 48, 24, 12};
__constant__ int c_PO[4] = {0, 6144, 7680, 8064};
__constant__ int c_OO[4] = {0, 81*6144, 81*7680, 81*8064};

// ---------------------------------------------------------------------------
// Kernel 1: transpose (D,HW)->(HW,D) fp32->fp16 both maps (768 blocks, two
// 32x32 tiles per block -> 2 independent LDG.128/thread) + coordsA (90 blocks).
// ---------------------------------------------------------------------------
#define TR_BLOCKS 768
#define CA_ELEMS (2*NPIX0 + 5376*2)
#define CA_BLOCKS ((CA_ELEMS + 255)/256)     // 90

__global__ void __launch_bounds__(256) k_prep(const float* __restrict__ f1,
                                              const float* __restrict__ f2,
                                              const float* __restrict__ crd) {
    int b = blockIdx.x;
    if (b < TR_BLOCKS) {
        __shared__ float tile[2][32 * 33];
        int bx = b % 192;            // pixel tile (32 px)
        int by = (b / 192) & 1;      // 64-channel tile
        int z  = b / 384;            // map
        const float* src = z ? f2 : f1;
        int p0 = bx * 32, d0 = by * 64;
        int drow = threadIdx.x >> 3;
        int px4  = threadIdx.x & 7;
        const float* s0 = src + (size_t)(d0 + drow) * NPIX0 + p0 + px4 * 4;
        float4 v0 = *(const float4*)(s0);
        float4 v1 = *(const float4*)(s0 + 32 * NPIX0);
        float* t0 = &tile[0][drow * 33 + px4 * 4];
        float* t1 = &tile[1][drow * 33 + px4 * 4];
        t0[0] = v0.x; t0[1] = v0.y; t0[2] = v0.z; t0[3] = v0.w;
        t1[0] = v1.x; t1[1] = v1.y; t1[2] = v1.z; t1[3] = v1.w;
        __syncthreads();
        __half* dst = z ? g_f2h : g_f1h;
        int sd = threadIdx.x & 15;
        int sp = threadIdx.x >> 4;
        #pragma unroll
        for (int k = 0; k < 2; k++) {
            #pragma unroll
            for (int i = 0; i < 2; i++) {
                int pl = sp + 16 * i;
                float lo = tile[k][(sd * 2)     * 33 + pl];
                float hi = tile[k][(sd * 2 + 1) * 33 + pl];
                *(__half2*)(dst + (size_t)(p0 + pl) * D + d0 + k * 32 + sd * 2) =
                    __floats2half2_rn(lo, hi);
            }
        }
        return;
    }
    // ---- coordsA: level-0 copy + x-axis triangle resize ----
    int idx = (b - TR_BLOCKS) * 256 + threadIdx.x;
    if (idx < 2 * NPIX0) {
        int q = idx >> 1, ax = idx & 1;
        g_crd[idx] = crd[ax * NPIX0 + q];
        return;
    }
    idx -= 2 * NPIX0;
    if (idx >= 5376 * 2) return;
    int p = idx >> 1, ax = idx & 1;
    int l, base;
    if      (p < 3072) { l = 1; base = 0;    }
    else if (p < 4608) { l = 2; base = 3072; }
    else               { l = 3; base = 4608; }
    int q  = p - base;
    int Wl = c_WL[l];
    int h  = q / Wl, w = q % Wl;
    float s   = (float)(1 << l);
    float cxx = (w + 0.5f) * s - 0.5f;
    int j0 = max(0,    (int)ceilf (cxx - s));
    int j1 = min(W0-1, (int)floorf(cxx + s));
    float sum = 0.f, acc = 0.f;
    for (int i = j0; i <= j1; i++) {
        float wgt = 1.f - fabsf(i - cxx) / s;
        sum += wgt;
        acc += wgt * crd[ax * NPIX0 + h * W0 + i];
    }
    g_tmpA[p * 2 + ax] = acc / sum;
}

// ---------------------------------------------------------------------------
// Kernel 2: hierarchical pool (levels 1..3, both maps; block <-> one 8x8
// level-0 region, uniform 4x float4 loads/thread) + coordsB. 208 blocks.
// ---------------------------------------------------------------------------
__global__ void __launch_bounds__(256) k_pool_cb() {
    int b = blockIdx.x;
    if (b < 192) {
        __shared__ float sm1[16 * 128];
        __shared__ float sm2[4 * 128];
        int m  = b >= 96;
        int p3 = m ? b - 96 : b;
        int h3 = p3 / 12, w3 = p3 % 12;
        __half* arr = m ? g_f2h : g_f1h;
        int t = threadIdx.x, grp = t & 15, l1 = t >> 4;
        int i1 = l1 >> 2, j1 = l1 & 3;
        int r0 = h3 * 8 + i1 * 2, c0 = w3 * 8 + j1 * 2;
        float2 a0 = {0,0}, a1 = {0,0}, a2 = {0,0}, a3 = {0,0};
        #pragma unroll
        for (int di = 0; di < 2; di++)
            #pragma unroll
            for (int dj = 0; dj < 2; dj++) {
                float4 hv = *(const float4*)(arr +
                    (size_t)((r0 + di) * W0 + (c0 + dj)) * D + grp * 8);
                const __half2* hh = (const __half2*)&hv;
                float2 v;
                v = __half22float2(hh[0]); a0.x += v.x; a0.y += v.y;
                v = __half22float2(hh[1]); a1.x += v.x; a1.y += v.y;
                v = __half22float2(hh[2]); a2.x += v.x; a2.y += v.y;
                v = __half22float2(hh[3]); a3.x += v.x; a3.y += v.y;
            }
        a0.x *= 0.25f; a0.y *= 0.25f; a1.x *= 0.25f; a1.y *= 0.25f;
        a2.x *= 0.25f; a2.y *= 0.25f; a3.x *= 0.25f; a3.y *= 0.25f;
        {
            __half2 r[4];
            r[0] = __floats2half2_rn(a0.x, a0.y);
            r[1] = __floats2half2_rn(a1.x, a1.y);
            r[2] = __floats2half2_rn(a2.x, a2.y);
            r[3] = __floats2half2_rn(a3.x, a3.y);
            int p1 = c_PO[1] + (h3 * 4 + i1) * 48 + (w3 * 4 + j1);
            *(float4*)(arr + (size_t)p1 * D + grp * 8) = *(float4*)r;
        }
        float* s1 = sm1 + l1 * 128 + grp * 8;
        s1[0] = a0.x; s1[1] = a0.y; s1[2] = a1.x; s1[3] = a1.y;
        s1[4] = a2.x; s1[5] = a2.y; s1[6] = a3.x; s1[7] = a3.y;
        __syncthreads();
        if (t < 64) {
            int g2 = t & 15, l2 = t >> 4;
            int i2 = l2 >> 1, j2 = l2 & 1;
            float acc[8];
            #pragma unroll
            for (int c = 0; c < 8; c++) acc[c] = 0.f;
            #pragma unroll
            for (int di = 0; di < 2; di++)
                #pragma unroll
                for (int dj = 0; dj < 2; dj++) {
                    const float* s = sm1 + ((2*i2 + di) * 4 + (2*j2 + dj)) * 128 + g2 * 8;
                    #pragma unroll
                    for (int c = 0; c < 8; c++) acc[c] += s[c];
                }
            __half2 r[4];
            #pragma unroll
            for (int c = 0; c < 4; c++)
                r[c] = __floats2half2_rn(acc[2*c] * 0.25f, acc[2*c+1] * 0.25f);
            int p2 = c_PO[2] + (h3 * 2 + i2) * 24 + (w3 * 2 + j2);
            *(float4*)(arr + (size_t)p2 * D + g2 * 8) = *(float4*)r;
            float* s2 = sm2 + l2 * 128 + g2 * 8;
            #pragma unroll
            for (int c = 0; c < 8; c++) s2[c] = acc[c] * 0.25f;
        }
        __syncthreads();
        if (t < 16) {
            float acc[8];
            #pragma unroll
            for (int c = 0; c < 8; c++) acc[c] = 0.f;
            #pragma unroll
            for (int l2 = 0; l2 < 4; l2++) {
                const float* s = sm2 + l2 * 128 + t * 8;
                #pragma unroll
                for (int c = 0; c < 8; c++) acc[c] += s[c];
            }
            __half2 r[4];
            #pragma unroll
            for (int c = 0; c < 4; c++)
                r[c] = __floats2half2_rn(acc[2*c] * 0.25f, acc[2*c+1] * 0.25f);
            int p3g = c_PO[3] + h3 * 12 + w3;
            *(float4*)(arr + (size_t)p3g * D + t * 8) = *(float4*)r;
        }
        return;
    }
    // ---- coordsB: y-axis resize + /2^l ----
    int idx = (b - 192) * 256 + threadIdx.x;
    if (idx >= 2016 * 2) return;
    int p = idx >> 1, ax = idx & 1;
    int l, base, abase;
    if      (p < 1536) { l = 1; base = 0;    abase = 0;    }
    else if (p < 1920) { l = 2; base = 1536; abase = 3072; }
    else               { l = 3; base = 1920; abase = 4608; }
    int q  = p - base;
    int Wl = c_WL[l];
    int h  = q / Wl, w = q % Wl;
    float s   = (float)(1 << l);
    float cyy = (h + 0.5f) * s - 0.5f;
    int j0 = max(0,    (int)ceilf (cyy - s));
    int j1 = min(H0-1, (int)floorf(cyy + s));
    float sum = 0.f, acc = 0.f;
    for (int j = j0; j <= j1; j++) {
        float wgt = 1.f - fabsf(j - cyy) / s;
        sum += wgt;
        acc += wgt * g_tmpA[(abase + j * Wl + w) * 2 + ax];
    }
    g_crd[(c_PO[l] + q) * 2 + ax] = acc / (sum * s);
}

// ---------------------------------------------------------------------------
// Kernel 3: fused local correlation, ALL levels, 1020 blocks (perfect balance).
// Warp<->pixel, 8-lane dot groups, ALU offsets.
// ---------------------------------------------------------------------------
#define TILE 8
__device__ __forceinline__ float dot8h(float4 a0, float4 a1, float4 hv) {
    const __half2* h = (const __half2*)&hv;
    float2 v0 = __half22float2(h[0]);
    float2 v1 = __half22float2(h[1]);
    float2 v2 = __half22float2(h[2]);
    float2 v3 = __half22float2(h[3]);
    return a0.x*v0.x + a0.y*v0.y + a0.z*v1.x + a0.w*v1.y
         + a1.x*v2.x + a1.y*v2.y + a1.z*v3.x + a1.w*v3.y;
}

__global__ void __launch_bounds__(256) k_corr_all(float* __restrict__ out) {
    int b = blockIdx.x;
    int l, tbase;
    if      (b < 768)  { l = 0; tbase = 0;    }
    else if (b < 960)  { l = 1; tbase = 768;  }
    else if (b < 1008) { l = 2; tbase = 960;  }
    else               { l = 3; tbase = 1008; }
    int Hl = c_HL[l], Wl = c_WL[l];
    int pixoff = c_PO[l];
    int HW = Hl * Wl;
    int pix0 = (b - tbase) * TILE;

    int tid   = threadIdx.x;
    int lane  = tid & 31, warp = tid >> 5;
    int lane8 = lane & 7, grp = lane >> 3;

    __shared__ float gsh[TILE * 100];
    __shared__ float fxs[TILE], fys[TILE];
    __shared__ int   bxs[TILE], bys[TILE];

    int pix = pix0 + warp;

    const __half* f1row = g_f1h + (size_t)(pixoff + pix) * D;
    float4 ha = *(const float4*)(f1row + lane8 * 8);
    float4 hb = *(const float4*)(f1row + 64 + lane8 * 8);
    float4 a0, a1, a2, a3;
    {
        const __half2* pa = (const __half2*)&ha;
        float2 q0 = __half22float2(pa[0]), q1 = __half22float2(pa[1]);
        float2 q2 = __half22float2(pa[2]), q3 = __half22float2(pa[3]);
        a0 = make_float4(q0.x, q0.y, q1.x, q1.y);
        a1 = make_float4(q2.x, q2.y, q3.x, q3.y);
        const __half2* pb = (const __half2*)&hb;
        q0 = __half22float2(pb[0]); q1 = __half22float2(pb[1]);
        q2 = __half22float2(pb[2]); q3 = __half22float2(pb[3]);
        a2 = make_float4(q0.x, q0.y, q1.x, q1.y);
        a3 = make_float4(q2.x, q2.y, q3.x, q3.y);
    }

    float cx = 0.f, cy = 0.f;
    if (lane == 0) {
        cx = g_crd[(pixoff + pix) * 2];
        cy = g_crd[(pixoff + pix) * 2 + 1];
    }
    cx = __shfl_sync(0xffffffffu, cx, 0);
    cy = __shfl_sync(0xffffffffu, cy, 0);
    float flx = floorf(cx), fly = floorf(cy);
    int bx = (int)flx, by = (int)fly;
    if (lane == 0) {
        bxs[warp] = bx; bys[warp] = by;
        fxs[warp] = cx - flx; fys[warp] = cy - fly;
    }

    const __half* f2lane = g_f2h + (size_t)pixoff * D + lane8 * 8;
    float* gsh100 = gsh + warp * 100;

    #pragma unroll 5
    for (int i = 0; i < 25; i++) {
        int pos = i * 4 + grp;
        int u = (pos * 205) >> 11;       // pos / 10
        int t = pos - u * 10;            // pos % 10
        int px = min(max(bx + t - 4, 0), Wl - 1);
        int py = min(max(by + u - 4, 0), Hl - 1);
        const __half* row = f2lane + (py * Wl + px) * D;
        float4 h0 = *(const float4*)(row);
        float4 h1 = *(const float4*)(row + 64);
        float s = dot8h(a0, a1, h0) + dot8h(a2, a3, h1);
        s += __shfl_xor_sync(0xffffffffu, s, 4);
        s += __shfl_xor_sync(0xffffffffu, s, 2);
        s += __shfl_xor_sync(0xffffffffu, s, 1);
        if (lane8 == 0) gsh100[pos] = s;
    }
    __syncthreads();

    #pragma unroll
    for (int idx = tid; idx < 81 * TILE; idx += 256) {
        int k = idx >> 3;
        int j = idx & (TILE - 1);
        int adx = k / 9;
        int bdy = k - adx * 9;
        int t0 = bxs[j] + adx - 4;
        int u0 = bys[j] + bdy - 4;
        float wx1 = (t0 < 0 || t0 >= Wl - 1) ? 0.f : fxs[j];
        float wy1 = (u0 < 0 || u0 >= Hl - 1) ? 0.f : fys[j];
        float wx0 = 1.f - wx1, wy0 = 1.f - wy1;
        const float* g = gsh + j * 100 + bdy * 10 + adx;
        float c = wy0 * (wx0 * g[0]  + wx1 * g[1])
                + wy1 * (wx0 * g[10] + wx1 * g[11]);
        out[c_OO[l] + k * HW + pix0 + j] = c * 0.08838834764831845f; // 1/sqrt(128)
    }
}

// ---------------------------------------------------------------------------
// Launch: single stream, 3 nodes, no events.
// ---------------------------------------------------------------------------
extern "C" void kernel_launch(void* const* d_in, const int* in_sizes, int n_in,
                              void* d_out, int out_size) {
    const float* f1  = (const float*)d_in[0];
    const float* f2  = (const float*)d_in[1];
    const float* crd = (const float*)d_in[2];
    float* out = (float*)d_out;

    k_prep<<<TR_BLOCKS + CA_BLOCKS, 256>>>(f1, f2, crd);
    k_pool_cb<<<208, 256>>>();
    k_corr_all<<<1020, 256>>>(out);
}